// round 9
// baseline (speedup 1.0000x reference)
#include <cuda_runtime.h>
#include <cuda_bf16.h>
#include <cuda_fp16.h>
#include <cstdint>

// Problem constants
#define Bn 4
#define Np 4096      // pixels per batch (64*64)
#define Cc 512
#define NW 640       // packed QKV output width: 64 f + 64 g + 512 v
#define NROWS (Bn*Np)
#define PSCALE 0.0625f   // P stored as exp(s)/16; cancels in P@V / rowsum(P)

// Scratch (static device allocations -- allowed)
__device__ __align__(1024) __half g_Xb[(size_t)NROWS * Cc];   // x in fp16
__device__ __align__(1024) __half g_Wt[(size_t)NW * Cc];      // packed weights [n][k]
__device__ __align__(1024) __half g_FG[(size_t)NROWS * 128];  // f (0-63), g (64-127)
__device__ __align__(1024) __half g_V [(size_t)Bn * Np * Cc]; // V natural [b][i][c]
__device__ __align__(1024) __half g_Vt[(size_t)Bn * Cc * Np]; // V transposed [b][c][i]
__device__ __align__(1024) __half g_P [(size_t)Bn * Np * Np]; // exp(S)/16, fp16
__device__ float g_l[NROWS];                                  // row sums of stored P

// ---------------------------------------------------------------------------
// mma.sync m16n8k16 fp16 -> fp16 accum
// ---------------------------------------------------------------------------
__device__ __forceinline__ void mma_f16(uint32_t c[2], const uint32_t a[4],
                                        uint32_t b0, uint32_t b1) {
    asm volatile(
        "mma.sync.aligned.m16n8k16.row.col.f16.f16.f16.f16 "
        "{%0,%1}, {%2,%3,%4,%5}, {%6,%7}, {%0,%1};\n"
        : "+r"(c[0]), "+r"(c[1])
        : "r"(a[0]), "r"(a[1]), "r"(a[2]), "r"(a[3]), "r"(b0), "r"(b1));
}
__device__ __forceinline__ void ldsm4(uint32_t* r, uint32_t addr) {
    asm volatile("ldmatrix.sync.aligned.m8n8.x4.shared.b16 {%0,%1,%2,%3}, [%4];"
                 : "=r"(r[0]), "=r"(r[1]), "=r"(r[2]), "=r"(r[3]) : "r"(addr));
}
__device__ __forceinline__ uint32_t smem_to_u32(const void* p) {
    uint32_t a;
    asm("{ .reg .u64 t; cvta.to.shared.u64 t, %1; cvt.u32.u64 %0, t; }" : "=r"(a) : "l"(p));
    return a;
}
__device__ __forceinline__ void cp16(uint32_t dst, const void* src) {
    asm volatile("cp.async.cg.shared.global [%0], [%1], 16;\n" :: "r"(dst), "l"(src));
}
#define CP_COMMIT() asm volatile("cp.async.commit_group;\n" ::: "memory")
#define CP_WAIT0()  asm volatile("cp.async.wait_group 0;\n" ::: "memory")

#define TKE    64                 // K-tile in fp16 elements (128 bytes per row)
#define TILEA  (256 * 128)        // A stage bytes: 256 rows x 128B (SW128)
#define TILEBB (128 * 128)        // B stage bytes: 128 rows x 128B
#define STAGEB (TILEA + TILEBB)   // 49152
#define GEMM_SMEM (2 * STAGEB)    // 98304 bytes -> 2 CTAs/SM

// Block tile 256x128, K-tile 64, 256 threads (8 warps, 4x2 grid, 64x64 each).
// SW128 XOR-swizzled stages, cp.async double buffer, ONE barrier per K-tile.
// Warp tile 64x64: 8 LDSM.x4 -> 32 MMA per k16 step (0.25 LDSM/MMA).
__device__ __forceinline__ void gemm_tile(
    const __half* __restrict__ Ag, int lda,
    const __half* __restrict__ Bg, int ldb,
    int K, uint32_t acc[4][8][2], __half* smem)
{
    const int tid = threadIdx.x, lane = tid & 31, warp = tid >> 5;
    const int wm = warp & 3, wn = warp >> 2;
    const uint32_t sbase = smem_to_u32(smem);
    const int srow = tid >> 3;          // staging row 0..31 (+32*q)
    const int schunk = tid & 7;         // 16B chunk within 128B row
    const int nk = K / TKE;

    const uint32_t l7  = lane & 7;
    const uint32_t hiA = lane >> 4;            // A: k-half from lane
    const uint32_t hiB = (lane >> 3) & 1;      // B: k-half from lane
    const uint32_t rowA = (uint32_t)(wm * 64 + ((lane >> 3) & 1) * 8) + l7;
    const uint32_t rowB = (uint32_t)(wn * 64 + (lane >> 4) * 8) + l7;

    auto issue = [&](int i) {
        const uint32_t sa = sbase + (uint32_t)((i & 1) * STAGEB);
        const uint32_t sb = sa + TILEA;
        const int k0 = i * TKE;
        const uint32_t pch = (uint32_t)(schunk ^ (srow & 7)) * 16;
        #pragma unroll
        for (int q = 0; q < 8; q++) {           // A: 256 rows
            const int row = srow + q * 32;
            cp16(sa + (uint32_t)row * 128 + pch,
                 (const char*)(Ag + (size_t)row * lda + k0) + schunk * 16);
        }
        #pragma unroll
        for (int q = 0; q < 4; q++) {           // B: 128 rows
            const int row = srow + q * 32;
            cp16(sb + (uint32_t)row * 128 + pch,
                 (const char*)(Bg + (size_t)row * ldb + k0) + schunk * 16);
        }
        CP_COMMIT();
    };

    issue(0);   // prologue

    for (int i = 0; i < nk; i++) {
        CP_WAIT0();
        __syncthreads();                 // single barrier per K-tile
        if (i + 1 < nk) issue(i + 1);

        const uint32_t bb = sbase + (uint32_t)((i & 1) * STAGEB);
        #pragma unroll
        for (int ks = 0; ks < 4; ks++) {             // four k16 steps
            const uint32_t pa = (((uint32_t)(2 * ks) + hiA) ^ l7) << 4;
            const uint32_t pb = (((uint32_t)(2 * ks) + hiB) ^ l7) << 4;
            uint32_t a[4][4], b4[4][4];
            #pragma unroll
            for (int mi = 0; mi < 4; mi++)
                ldsm4(a[mi], bb + (rowA + (uint32_t)(mi * 16)) * 128 + pa);
            #pragma unroll
            for (int jp = 0; jp < 4; jp++)
                ldsm4(b4[jp], bb + TILEA + (rowB + (uint32_t)(jp * 16)) * 128 + pb);
            #pragma unroll
            for (int mi = 0; mi < 4; mi++)
                #pragma unroll
                for (int jp = 0; jp < 4; jp++) {
                    mma_f16(acc[mi][2 * jp],     a[mi], b4[jp][0], b4[jp][1]);
                    mma_f16(acc[mi][2 * jp + 1], a[mi], b4[jp][2], b4[jp][3]);
                }
        }
    }
    __syncthreads();
}

// ---------------------------------------------------------------------------
// Prep kernels
// ---------------------------------------------------------------------------
__global__ void convert_x(const float* __restrict__ x) {
    size_t i = (size_t)blockIdx.x * 256 + threadIdx.x;
    float4 v = ((const float4*)x)[i];
    __half2 p0 = __floats2half2_rn(v.x, v.y);
    __half2 p1 = __floats2half2_rn(v.z, v.w);
    ((__half2*)g_Xb)[2 * i]     = p0;
    ((__half2*)g_Xb)[2 * i + 1] = p1;
}

__global__ void pack_w(const float* __restrict__ kf, const float* __restrict__ kg,
                       const float* __restrict__ kh) {
    int idx = blockIdx.x * 256 + threadIdx.x;
    int n = idx >> 9, k = idx & 511;
    float v;
    if (n < 64)       v = kf[k * 64 + n];
    else if (n < 128) v = kg[k * 64 + (n - 64)];
    else              v = kh[k * 512 + (n - 128)];
    g_Wt[idx] = __float2half(v);
}

__global__ void zero_l() {
    int i = blockIdx.x * 1024 + threadIdx.x;
    if (i < NROWS) g_l[i] = 0.f;
}

// ---------------------------------------------------------------------------
// GEMM 1: [f|g|v] = Xb @ W ; f/g -> g_FG, v -> g_V (natural, coalesced)
// ---------------------------------------------------------------------------
__global__ void __launch_bounds__(256, 2) gemm1_qkv() {
    extern __shared__ __half smem[];
    uint32_t acc[4][8][2];
    #pragma unroll
    for (int i = 0; i < 4; i++)
        #pragma unroll
        for (int j = 0; j < 8; j++) { acc[i][j][0] = 0u; acc[i][j][1] = 0u; }

    const int m0 = blockIdx.y * 256, n0 = blockIdx.x * 128;
    gemm_tile(g_Xb + (size_t)m0 * Cc, Cc, g_Wt + (size_t)n0 * Cc, Cc, Cc, acc, smem);

    const int lane = threadIdx.x & 31, warp = threadIdx.x >> 5;
    const int wm = warp & 3, wn = warp >> 2, g = lane >> 2, t4 = lane & 3;
    #pragma unroll
    for (int mi = 0; mi < 4; mi++) {
        #pragma unroll
        for (int h = 0; h < 2; h++) {
            int r = m0 + wm * 64 + mi * 16 + g + h * 8;
            #pragma unroll
            for (int j = 0; j < 8; j++) {
                int c = n0 + wn * 64 + j * 8 + 2 * t4;
                uint32_t p = acc[mi][j][h];         // half2 at (r, c..c+1)
                if (n0 == 0) *(uint32_t*)&g_FG[(size_t)r * 128 + c] = p;
                else         *(uint32_t*)&g_V [(size_t)r * Cc + (c - 128)] = p;
            }
        }
    }
}

// ---------------------------------------------------------------------------
// Transpose V [b][i][c] -> Vt [b][c][i] (smem tiled, coalesced both sides)
// ---------------------------------------------------------------------------
__global__ void vtrans() {
    __shared__ __half t[64 * 72];
    const int bb = blockIdx.z, it = blockIdx.x, ct = blockIdx.y;
    const __half* src = g_V + ((size_t)bb * Np + it * 64) * Cc + ct * 64;
    #pragma unroll
    for (int k = 0; k < 2; k++) {
        int u = threadIdx.x + k * 256;
        int row = u >> 3, c8 = (u & 7) * 8;
        *(uint4*)(t + row * 72 + c8) = *(const uint4*)(src + (size_t)row * Cc + c8);
    }
    __syncthreads();
    __half* dst = g_Vt + ((size_t)bb * Cc + ct * 64) * Np + it * 64;
    #pragma unroll
    for (int k = 0; k < 2; k++) {
        int u = threadIdx.x + k * 256;
        int orow = u >> 3, i8 = (u & 7) * 8;
        __half tmp[8];
        #pragma unroll
        for (int q = 0; q < 8; q++) tmp[q] = t[(i8 + q) * 72 + orow];
        *(uint4*)(dst + (size_t)orow * Np + i8) = *(uint4*)tmp;
    }
}

// ---------------------------------------------------------------------------
// GEMM 2: P = exp(F @ G^T)/16 per batch, + fused row-sum atomics
// ---------------------------------------------------------------------------
__global__ void __launch_bounds__(256, 2) gemm2_score() {
    extern __shared__ __half smem[];
    uint32_t acc[4][8][2];
    #pragma unroll
    for (int i = 0; i < 4; i++)
        #pragma unroll
        for (int j = 0; j < 8; j++) { acc[i][j][0] = 0u; acc[i][j][1] = 0u; }

    const int n0 = blockIdx.x * 128, m0 = blockIdx.y * 256, bb = blockIdx.z;
    const __half* A  = g_FG + ((size_t)bb * Np + m0) * 128;       // f
    const __half* Bp = g_FG + ((size_t)bb * Np + n0) * 128 + 64;  // g
    gemm_tile(A, 128, Bp, 128, 64, acc, smem);

    __half* Pb = g_P + (size_t)bb * Np * Np;
    const int lane = threadIdx.x & 31, warp = threadIdx.x >> 5;
    const int wm = warp & 3, wn = warp >> 2, g = lane >> 2, t4 = lane & 3;

    #pragma unroll
    for (int mi = 0; mi < 4; mi++) {
        #pragma unroll
        for (int h = 0; h < 2; h++) {
            int r = m0 + wm * 64 + mi * 16 + g + h * 8;
            float rs = 0.f;
            #pragma unroll
            for (int j = 0; j < 8; j++) {
                int c = n0 + wn * 64 + j * 8 + 2 * t4;
                float2 s2 = __half22float2(*(__half2*)&acc[mi][j][h]);
                __half2 ph = __floats2half2_rn(__expf(s2.x) * PSCALE,
                                               __expf(s2.y) * PSCALE);
                *(__half2*)&Pb[(size_t)r * Np + c] = ph;
                float2 pf = __half22float2(ph);   // round-tripped for exact l
                rs += pf.x + pf.y;
            }
            rs += __shfl_down_sync(0xffffffffu, rs, 2, 4);
            rs += __shfl_down_sync(0xffffffffu, rs, 1, 4);
            if (t4 == 0) atomicAdd(&g_l[(size_t)bb * Np + r], rs);
        }
    }
}

// ---------------------------------------------------------------------------
// GEMM 3: out = gamma * (P @ Vt^T) / l + x   (per batch 4096x512, K=4096)
// ---------------------------------------------------------------------------
__global__ void __launch_bounds__(256, 2) gemm3_out(
    const float* __restrict__ x, const float* __restrict__ gamma,
    float* __restrict__ out)
{
    extern __shared__ __half smem[];
    uint32_t acc[4][8][2];
    #pragma unroll
    for (int i = 0; i < 4; i++)
        #pragma unroll
        for (int j = 0; j < 8; j++) { acc[i][j][0] = 0u; acc[i][j][1] = 0u; }

    const int n0 = blockIdx.x * 128, m0 = blockIdx.y * 256, bb = blockIdx.z;
    const __half* A  = g_P  + ((size_t)bb * Np + m0) * Np;
    const __half* Bp = g_Vt + ((size_t)bb * Cc + n0) * Np;
    gemm_tile(A, Np, Bp, Np, Np, acc, smem);

    const float gam = gamma[0];
    const int lane = threadIdx.x & 31, warp = threadIdx.x >> 5;
    const int wm = warp & 3, wn = warp >> 2, g = lane >> 2, t4 = lane & 3;

    #pragma unroll
    for (int mi = 0; mi < 4; mi++) {
        #pragma unroll
        for (int h = 0; h < 2; h++) {
            int r = bb * Np + m0 + wm * 64 + mi * 16 + g + h * 8;
            float inv = gam / g_l[r];
            #pragma unroll
            for (int j = 0; j < 8; j++) {
                int c = n0 + wn * 64 + j * 8 + 2 * t4;
                size_t o = (size_t)r * Cc + c;
                float2 a2 = __half22float2(*(__half2*)&acc[mi][j][h]);
                float2 xv = *(const float2*)(x + o);
                float2 ov;
                ov.x = a2.x * inv + xv.x;
                ov.y = a2.y * inv + xv.y;
                *(float2*)(out + o) = ov;
            }
        }
    }
}

// ===========================================================================
extern "C" void kernel_launch(void* const* d_in, const int* in_sizes, int n_in,
                              void* d_out, int out_size) {
    const float* x     = (const float*)d_in[0];
    const float* kf    = (const float*)d_in[1];
    const float* kg    = (const float*)d_in[2];
    const float* kh    = (const float*)d_in[3];
    const float* gamma = (const float*)d_in[4];
    float* out = (float*)d_out;

    static bool attr_done = false;
    if (!attr_done) {
        cudaFuncSetAttribute(gemm1_qkv,   cudaFuncAttributeMaxDynamicSharedMemorySize, GEMM_SMEM);
        cudaFuncSetAttribute(gemm2_score, cudaFuncAttributeMaxDynamicSharedMemorySize, GEMM_SMEM);
        cudaFuncSetAttribute(gemm3_out,   cudaFuncAttributeMaxDynamicSharedMemorySize, GEMM_SMEM);
        attr_done = true;
    }

    convert_x<<<(NROWS * Cc / 4) / 256, 256>>>(x);
    pack_w<<<(NW * Cc) / 256, 256>>>(kf, kg, kh);
    zero_l<<<16, 1024>>>();
    gemm1_qkv<<<dim3(NW / 128, NROWS / 256), 256, GEMM_SMEM>>>();
    vtrans<<<dim3(64, 8, 4), 256>>>();
    gemm2_score<<<dim3(Np / 128, Np / 256, Bn), 256, GEMM_SMEM>>>();
    gemm3_out<<<dim3(Cc / 128, Np / 256, Bn), 256, GEMM_SMEM>>>(x, gamma, out);
}

// round 10
// speedup vs baseline: 1.0327x; 1.0327x over previous
#include <cuda_runtime.h>
#include <cuda_bf16.h>
#include <cuda_fp16.h>
#include <cstdint>

// Problem constants
#define Bn 4
#define Np 4096      // pixels per batch (64*64)
#define Cc 512
#define NW 640       // packed QKV output width: 64 f + 64 g + 512 v
#define NROWS (Bn*Np)
#define PSCALE 0.0625f   // P stored as exp(s)/16; cancels in P@V / rowsum(P)
#define KSPLIT 4         // gemm3 split-K factor (wave-quantization fix)

// Scratch (static device allocations -- allowed)
__device__ __align__(1024) __half g_Xb[(size_t)NROWS * Cc];   // x in fp16
__device__ __align__(1024) __half g_Wt[(size_t)NW * Cc];      // packed weights [n][k]
__device__ __align__(1024) __half g_FG[(size_t)NROWS * 128];  // f (0-63), g (64-127)
__device__ __align__(1024) __half g_V [(size_t)Bn * Np * Cc]; // V natural [b][i][c]
__device__ __align__(1024) __half g_Vt[(size_t)Bn * Cc * Np]; // V transposed [b][c][i]
__device__ __align__(1024) __half g_P [(size_t)Bn * Np * Np]; // exp(S)/16, fp16
__device__ float g_l[NROWS];                                  // row sums of stored P

// ---------------------------------------------------------------------------
// mma.sync m16n8k16 fp16 -> fp16 accum
// ---------------------------------------------------------------------------
__device__ __forceinline__ void mma_f16(uint32_t c[2], const uint32_t a[4],
                                        uint32_t b0, uint32_t b1) {
    asm volatile(
        "mma.sync.aligned.m16n8k16.row.col.f16.f16.f16.f16 "
        "{%0,%1}, {%2,%3,%4,%5}, {%6,%7}, {%0,%1};\n"
        : "+r"(c[0]), "+r"(c[1])
        : "r"(a[0]), "r"(a[1]), "r"(a[2]), "r"(a[3]), "r"(b0), "r"(b1));
}
__device__ __forceinline__ void ldsm4(uint32_t* r, uint32_t addr) {
    asm volatile("ldmatrix.sync.aligned.m8n8.x4.shared.b16 {%0,%1,%2,%3}, [%4];"
                 : "=r"(r[0]), "=r"(r[1]), "=r"(r[2]), "=r"(r[3]) : "r"(addr));
}
__device__ __forceinline__ uint32_t smem_to_u32(const void* p) {
    uint32_t a;
    asm("{ .reg .u64 t; cvta.to.shared.u64 t, %1; cvt.u32.u64 %0, t; }" : "=r"(a) : "l"(p));
    return a;
}
__device__ __forceinline__ void cp16(uint32_t dst, const void* src) {
    asm volatile("cp.async.cg.shared.global [%0], [%1], 16;\n" :: "r"(dst), "l"(src));
}
#define CP_COMMIT() asm volatile("cp.async.commit_group;\n" ::: "memory")
#define CP_WAIT0()  asm volatile("cp.async.wait_group 0;\n" ::: "memory")

#define TKE   64                 // K-tile in fp16 elements (128 bytes per row)
#define TILEB (128 * 128)        // bytes per staged tile (128 rows x 128B, SW128)
#define GEMM_SMEM (2 * 2 * TILEB)   // 65536 bytes -> 3 CTAs/SM

// Block tile 128x128, K-tile 64, 256 threads (8 warps, 4x2 grid, 32x64 each).
// SW128 XOR-swizzled stages, cp.async double buffer, ONE barrier per K-tile.
// (R8 core: proven 321.5us config)
__device__ __forceinline__ void gemm_tile(
    const __half* __restrict__ Ag, int lda,
    const __half* __restrict__ Bg, int ldb,
    int K, uint32_t acc[2][8][2], __half* smem)
{
    const int tid = threadIdx.x, lane = tid & 31, warp = tid >> 5;
    const int wm = warp & 3, wn = warp >> 2;
    const uint32_t sbase = smem_to_u32(smem);
    const int srow = tid >> 3;          // staging row 0..31 (+32*q)
    const int schunk = tid & 7;         // 16B chunk within 128B row
    const int nk = K / TKE;

    const uint32_t l7  = lane & 7;
    const uint32_t hiA = lane >> 4;            // A: k-half from lane
    const uint32_t hiB = (lane >> 3) & 1;      // B: k-half from lane
    const uint32_t rowA = (uint32_t)(wm * 32 + ((lane >> 3) & 1) * 8) + l7;
    const uint32_t rowB = (uint32_t)(wn * 64 + (lane >> 4) * 8) + l7;

    auto issue = [&](int i) {
        const uint32_t sa = sbase + (uint32_t)((i & 1) * 2 * TILEB);
        const uint32_t sb = sa + TILEB;
        const int k0 = i * TKE;
        const uint32_t pch = (uint32_t)(schunk ^ (srow & 7)) * 16;
        #pragma unroll
        for (int q = 0; q < 4; q++) {
            const int row = srow + q * 32;
            const uint32_t soff = (uint32_t)row * 128 + pch;
            cp16(sa + soff, (const char*)(Ag + (size_t)row * lda + k0) + schunk * 16);
            cp16(sb + soff, (const char*)(Bg + (size_t)row * ldb + k0) + schunk * 16);
        }
        CP_COMMIT();
    };

    issue(0);   // prologue

    for (int i = 0; i < nk; i++) {
        CP_WAIT0();
        __syncthreads();                 // single barrier per K-tile
        if (i + 1 < nk) issue(i + 1);

        const uint32_t bb = sbase + (uint32_t)((i & 1) * 2 * TILEB);
        #pragma unroll
        for (int ks = 0; ks < 4; ks++) {             // four k16 steps
            const uint32_t pa = (((uint32_t)(2 * ks) + hiA) ^ l7) << 4;
            const uint32_t pb = (((uint32_t)(2 * ks) + hiB) ^ l7) << 4;
            uint32_t a[2][4], b4[4][4];
            ldsm4(a[0], bb + rowA * 128 + pa);
            ldsm4(a[1], bb + (rowA + 16) * 128 + pa);
            #pragma unroll
            for (int jp = 0; jp < 4; jp++)
                ldsm4(b4[jp], bb + TILEB + (rowB + (uint32_t)(jp * 16)) * 128 + pb);
            #pragma unroll
            for (int ii = 0; ii < 2; ii++)
                #pragma unroll
                for (int jp = 0; jp < 4; jp++) {
                    mma_f16(acc[ii][2 * jp],     a[ii], b4[jp][0], b4[jp][1]);
                    mma_f16(acc[ii][2 * jp + 1], a[ii], b4[jp][2], b4[jp][3]);
                }
        }
    }
    __syncthreads();
}

// ---------------------------------------------------------------------------
// Prep kernels
// ---------------------------------------------------------------------------
// convert x -> fp16 AND pre-initialize out = x (gemm3 splits atomicAdd into it)
__global__ void convert_x(const float* __restrict__ x, float* __restrict__ out) {
    size_t i = (size_t)blockIdx.x * 256 + threadIdx.x;
    float4 v = ((const float4*)x)[i];
    ((float4*)out)[i] = v;
    __half2 p0 = __floats2half2_rn(v.x, v.y);
    __half2 p1 = __floats2half2_rn(v.z, v.w);
    ((__half2*)g_Xb)[2 * i]     = p0;
    ((__half2*)g_Xb)[2 * i + 1] = p1;
}

__global__ void pack_w(const float* __restrict__ kf, const float* __restrict__ kg,
                       const float* __restrict__ kh) {
    int idx = blockIdx.x * 256 + threadIdx.x;
    int n = idx >> 9, k = idx & 511;
    float v;
    if (n < 64)       v = kf[k * 64 + n];
    else if (n < 128) v = kg[k * 64 + (n - 64)];
    else              v = kh[k * 512 + (n - 128)];
    g_Wt[idx] = __float2half(v);
    if (idx < NROWS) g_l[idx] = 0.f;       // folded zero_l
}

// ---------------------------------------------------------------------------
// GEMM 1: [f|g|v] = Xb @ W ; f/g -> g_FG, v -> g_V (natural, coalesced)
// ---------------------------------------------------------------------------
__global__ void __launch_bounds__(256, 3) gemm1_qkv() {
    extern __shared__ __half smem[];
    uint32_t acc[2][8][2];
    #pragma unroll
    for (int i = 0; i < 2; i++)
        #pragma unroll
        for (int j = 0; j < 8; j++) { acc[i][j][0] = 0u; acc[i][j][1] = 0u; }

    const int m0 = blockIdx.y * 128, n0 = blockIdx.x * 128;
    gemm_tile(g_Xb + (size_t)m0 * Cc, Cc, g_Wt + (size_t)n0 * Cc, Cc, Cc, acc, smem);

    const int lane = threadIdx.x & 31, warp = threadIdx.x >> 5;
    const int wm = warp & 3, wn = warp >> 2, g = lane >> 2, t4 = lane & 3;
    #pragma unroll
    for (int i = 0; i < 2; i++) {
        #pragma unroll
        for (int h = 0; h < 2; h++) {
            int r = m0 + wm * 32 + i * 16 + g + h * 8;
            #pragma unroll
            for (int j = 0; j < 8; j++) {
                int c = n0 + wn * 64 + j * 8 + 2 * t4;
                uint32_t p = acc[i][j][h];          // half2 at (r, c..c+1)
                if (n0 == 0) *(uint32_t*)&g_FG[(size_t)r * 128 + c] = p;
                else         *(uint32_t*)&g_V [(size_t)r * Cc + (c - 128)] = p;
            }
        }
    }
}

// ---------------------------------------------------------------------------
// Transpose V [b][i][c] -> Vt [b][c][i] (smem tiled, coalesced both sides)
// ---------------------------------------------------------------------------
__global__ void vtrans() {
    __shared__ __half t[64 * 72];
    const int bb = blockIdx.z, it = blockIdx.x, ct = blockIdx.y;
    const __half* src = g_V + ((size_t)bb * Np + it * 64) * Cc + ct * 64;
    #pragma unroll
    for (int k = 0; k < 2; k++) {
        int u = threadIdx.x + k * 256;
        int row = u >> 3, c8 = (u & 7) * 8;
        *(uint4*)(t + row * 72 + c8) = *(const uint4*)(src + (size_t)row * Cc + c8);
    }
    __syncthreads();
    __half* dst = g_Vt + ((size_t)bb * Cc + ct * 64) * Np + it * 64;
    #pragma unroll
    for (int k = 0; k < 2; k++) {
        int u = threadIdx.x + k * 256;
        int orow = u >> 3, i8 = (u & 7) * 8;
        __half tmp[8];
        #pragma unroll
        for (int q = 0; q < 8; q++) tmp[q] = t[(i8 + q) * 72 + orow];
        *(uint4*)(dst + (size_t)orow * Np + i8) = *(uint4*)tmp;
    }
}

// ---------------------------------------------------------------------------
// GEMM 2: P = exp(F @ G^T)/16 per batch, + fused row-sum atomics
// ---------------------------------------------------------------------------
__global__ void __launch_bounds__(256, 3) gemm2_score() {
    extern __shared__ __half smem[];
    uint32_t acc[2][8][2];
    #pragma unroll
    for (int i = 0; i < 2; i++)
        #pragma unroll
        for (int j = 0; j < 8; j++) { acc[i][j][0] = 0u; acc[i][j][1] = 0u; }

    const int n0 = blockIdx.x * 128, m0 = blockIdx.y * 128, bb = blockIdx.z;
    const __half* A  = g_FG + ((size_t)bb * Np + m0) * 128;       // f
    const __half* Bp = g_FG + ((size_t)bb * Np + n0) * 128 + 64;  // g
    gemm_tile(A, 128, Bp, 128, 64, acc, smem);

    __half* Pb = g_P + (size_t)bb * Np * Np;
    const int lane = threadIdx.x & 31, warp = threadIdx.x >> 5;
    const int wm = warp & 3, wn = warp >> 2, g = lane >> 2, t4 = lane & 3;

    #pragma unroll
    for (int i = 0; i < 2; i++) {
        #pragma unroll
        for (int h = 0; h < 2; h++) {
            int r = m0 + wm * 32 + i * 16 + g + h * 8;
            float rs = 0.f;
            #pragma unroll
            for (int j = 0; j < 8; j++) {
                int c = n0 + wn * 64 + j * 8 + 2 * t4;
                float2 s2 = __half22float2(*(__half2*)&acc[i][j][h]);
                __half2 ph = __floats2half2_rn(__expf(s2.x) * PSCALE,
                                               __expf(s2.y) * PSCALE);
                *(__half2*)&Pb[(size_t)r * Np + c] = ph;
                float2 pf = __half22float2(ph);   // round-tripped for exact l
                rs += pf.x + pf.y;
            }
            rs += __shfl_down_sync(0xffffffffu, rs, 2, 4);
            rs += __shfl_down_sync(0xffffffffu, rs, 1, 4);
            if (t4 == 0) atomicAdd(&g_l[(size_t)bb * Np + r], rs);
        }
    }
}

// ---------------------------------------------------------------------------
// GEMM 3 (split-K=4): out += gamma * (P @ Vt^T)_partial / l
// out pre-initialized to x in convert_x. blockIdx.z = b*KSPLIT + s.
// 2048 CTAs of K=1024 each -> better wave balance (444 slots).
// ---------------------------------------------------------------------------
__global__ void __launch_bounds__(256, 3) gemm3_out(
    const float* __restrict__ gamma, float* __restrict__ out)
{
    extern __shared__ __half smem[];
    uint32_t acc[2][8][2];
    #pragma unroll
    for (int i = 0; i < 2; i++)
        #pragma unroll
        for (int j = 0; j < 8; j++) { acc[i][j][0] = 0u; acc[i][j][1] = 0u; }

    const int n0 = blockIdx.x * 128, m0 = blockIdx.y * 128;
    const int bb = blockIdx.z / KSPLIT, sp = blockIdx.z % KSPLIT;
    const int kof = sp * (Np / KSPLIT);          // 1024-wide K slice
    const __half* A  = g_P  + ((size_t)bb * Np + m0) * Np + kof;
    const __half* Bp = g_Vt + ((size_t)bb * Cc + n0) * Np + kof;
    gemm_tile(A, Np, Bp, Np, Np / KSPLIT, acc, smem);

    const float gam = gamma[0];
    const int lane = threadIdx.x & 31, warp = threadIdx.x >> 5;
    const int wm = warp & 3, wn = warp >> 2, g = lane >> 2, t4 = lane & 3;

    #pragma unroll
    for (int i = 0; i < 2; i++) {
        #pragma unroll
        for (int h = 0; h < 2; h++) {
            int r = bb * Np + m0 + wm * 32 + i * 16 + g + h * 8;
            float inv = gam / g_l[r];
            #pragma unroll
            for (int j = 0; j < 8; j++) {
                int c = n0 + wn * 64 + j * 8 + 2 * t4;
                size_t o = (size_t)r * Cc + c;
                float2 a2 = __half22float2(*(__half2*)&acc[i][j][h]);
                atomicAdd(&out[o],     a2.x * inv);
                atomicAdd(&out[o + 1], a2.y * inv);
            }
        }
    }
}

// ===========================================================================
extern "C" void kernel_launch(void* const* d_in, const int* in_sizes, int n_in,
                              void* d_out, int out_size) {
    const float* x     = (const float*)d_in[0];
    const float* kf    = (const float*)d_in[1];
    const float* kg    = (const float*)d_in[2];
    const float* kh    = (const float*)d_in[3];
    const float* gamma = (const float*)d_in[4];
    float* out = (float*)d_out;

    static bool attr_done = false;
    if (!attr_done) {
        cudaFuncSetAttribute(gemm1_qkv,   cudaFuncAttributeMaxDynamicSharedMemorySize, GEMM_SMEM);
        cudaFuncSetAttribute(gemm2_score, cudaFuncAttributeMaxDynamicSharedMemorySize, GEMM_SMEM);
        cudaFuncSetAttribute(gemm3_out,   cudaFuncAttributeMaxDynamicSharedMemorySize, GEMM_SMEM);
        attr_done = true;
    }

    convert_x<<<(NROWS * Cc / 4) / 256, 256>>>(x, out);   // also: out = x
    pack_w<<<(NW * Cc) / 256, 256>>>(kf, kg, kh);         // also: g_l = 0
    gemm1_qkv<<<dim3(NW / 128, NROWS / 128), 256, GEMM_SMEM>>>();
    vtrans<<<dim3(64, 8, 4), 256>>>();
    gemm2_score<<<dim3(Np / 128, Np / 128, Bn), 256, GEMM_SMEM>>>();
    gemm3_out<<<dim3(Cc / 128, Np / 128, Bn * KSPLIT), 256, GEMM_SMEM>>>(gamma, out);
}

// round 11
// speedup vs baseline: 1.0748x; 1.0408x over previous
#include <cuda_runtime.h>
#include <cuda_bf16.h>
#include <cuda_fp16.h>
#include <cstdint>

// Problem constants
#define Bn 4
#define Np 4096      // pixels per batch (64*64)
#define Cc 512
#define NW 640       // packed QKV output width: 64 f + 64 g + 512 v
#define NROWS (Bn*Np)
#define KSPLIT 4         // gemm3 split-K factor (wave-quantization fix)
// P stored as exp(s)/16 = 2^(s*log2e - 4); the /16 cancels in P@V / rowsum(P)

// Scratch (static device allocations -- allowed)
__device__ __align__(1024) __half g_Xb[(size_t)NROWS * Cc];   // x in fp16
__device__ __align__(1024) __half g_Wt[(size_t)NW * Cc];      // packed weights [n][k]
__device__ __align__(1024) __half g_FG[(size_t)NROWS * 128];  // f (0-63), g (64-127)
__device__ __align__(1024) __half g_V [(size_t)Bn * Np * Cc]; // V natural [b][i][c]
__device__ __align__(1024) __half g_Vt[(size_t)Bn * Cc * Np]; // V transposed [b][c][i]
__device__ __align__(1024) __half g_P [(size_t)Bn * Np * Np]; // exp(S)/16, fp16
__device__ float g_l[NROWS];                                  // row sums of stored P

// ---------------------------------------------------------------------------
// mma.sync m16n8k16 fp16 -> fp16 accum
// ---------------------------------------------------------------------------
__device__ __forceinline__ void mma_f16(uint32_t c[2], const uint32_t a[4],
                                        uint32_t b0, uint32_t b1) {
    asm volatile(
        "mma.sync.aligned.m16n8k16.row.col.f16.f16.f16.f16 "
        "{%0,%1}, {%2,%3,%4,%5}, {%6,%7}, {%0,%1};\n"
        : "+r"(c[0]), "+r"(c[1])
        : "r"(a[0]), "r"(a[1]), "r"(a[2]), "r"(a[3]), "r"(b0), "r"(b1));
}
__device__ __forceinline__ void ldsm4(uint32_t* r, uint32_t addr) {
    asm volatile("ldmatrix.sync.aligned.m8n8.x4.shared.b16 {%0,%1,%2,%3}, [%4];"
                 : "=r"(r[0]), "=r"(r[1]), "=r"(r[2]), "=r"(r[3]) : "r"(addr));
}
__device__ __forceinline__ uint32_t smem_to_u32(const void* p) {
    uint32_t a;
    asm("{ .reg .u64 t; cvta.to.shared.u64 t, %1; cvt.u32.u64 %0, t; }" : "=r"(a) : "l"(p));
    return a;
}
__device__ __forceinline__ void cp16(uint32_t dst, const void* src) {
    asm volatile("cp.async.cg.shared.global [%0], [%1], 16;\n" :: "r"(dst), "l"(src));
}
#define CP_COMMIT() asm volatile("cp.async.commit_group;\n" ::: "memory")
#define CP_WAIT0()  asm volatile("cp.async.wait_group 0;\n" ::: "memory")

#define TKE   64                 // K-tile in fp16 elements (128 bytes per row)
#define TILEB (128 * 128)        // bytes per staged tile (128 rows x 128B, SW128)
#define GEMM_SMEM (2 * 2 * TILEB)   // 65536 bytes -> 3 CTAs/SM

// Block tile 128x128, K-tile 64, 256 threads (8 warps, 4x2 grid, 32x64 each).
// SW128 XOR-swizzled stages, cp.async double buffer, ONE barrier per K-tile.
// (R8 core: proven config -- unchanged)
__device__ __forceinline__ void gemm_tile(
    const __half* __restrict__ Ag, int lda,
    const __half* __restrict__ Bg, int ldb,
    int K, uint32_t acc[2][8][2], __half* smem)
{
    const int tid = threadIdx.x, lane = tid & 31, warp = tid >> 5;
    const int wm = warp & 3, wn = warp >> 2;
    const uint32_t sbase = smem_to_u32(smem);
    const int srow = tid >> 3;          // staging row 0..31 (+32*q)
    const int schunk = tid & 7;         // 16B chunk within 128B row
    const int nk = K / TKE;

    const uint32_t l7  = lane & 7;
    const uint32_t hiA = lane >> 4;            // A: k-half from lane
    const uint32_t hiB = (lane >> 3) & 1;      // B: k-half from lane
    const uint32_t rowA = (uint32_t)(wm * 32 + ((lane >> 3) & 1) * 8) + l7;
    const uint32_t rowB = (uint32_t)(wn * 64 + (lane >> 4) * 8) + l7;

    auto issue = [&](int i) {
        const uint32_t sa = sbase + (uint32_t)((i & 1) * 2 * TILEB);
        const uint32_t sb = sa + TILEB;
        const int k0 = i * TKE;
        const uint32_t pch = (uint32_t)(schunk ^ (srow & 7)) * 16;
        #pragma unroll
        for (int q = 0; q < 4; q++) {
            const int row = srow + q * 32;
            const uint32_t soff = (uint32_t)row * 128 + pch;
            cp16(sa + soff, (const char*)(Ag + (size_t)row * lda + k0) + schunk * 16);
            cp16(sb + soff, (const char*)(Bg + (size_t)row * ldb + k0) + schunk * 16);
        }
        CP_COMMIT();
    };

    issue(0);   // prologue

    for (int i = 0; i < nk; i++) {
        CP_WAIT0();
        __syncthreads();                 // single barrier per K-tile
        if (i + 1 < nk) issue(i + 1);

        const uint32_t bb = sbase + (uint32_t)((i & 1) * 2 * TILEB);
        #pragma unroll
        for (int ks = 0; ks < 4; ks++) {             // four k16 steps
            const uint32_t pa = (((uint32_t)(2 * ks) + hiA) ^ l7) << 4;
            const uint32_t pb = (((uint32_t)(2 * ks) + hiB) ^ l7) << 4;
            uint32_t a[2][4], b4[4][4];
            ldsm4(a[0], bb + rowA * 128 + pa);
            ldsm4(a[1], bb + (rowA + 16) * 128 + pa);
            #pragma unroll
            for (int jp = 0; jp < 4; jp++)
                ldsm4(b4[jp], bb + TILEB + (rowB + (uint32_t)(jp * 16)) * 128 + pb);
            #pragma unroll
            for (int ii = 0; ii < 2; ii++)
                #pragma unroll
                for (int jp = 0; jp < 4; jp++) {
                    mma_f16(acc[ii][2 * jp],     a[ii], b4[jp][0], b4[jp][1]);
                    mma_f16(acc[ii][2 * jp + 1], a[ii], b4[jp][2], b4[jp][3]);
                }
        }
    }
    __syncthreads();
}

// ---------------------------------------------------------------------------
// Prep kernels
// ---------------------------------------------------------------------------
// convert x -> fp16 AND pre-initialize out = x (gemm3 splits atomicAdd into it)
__global__ void convert_x(const float* __restrict__ x, float* __restrict__ out) {
    size_t i = (size_t)blockIdx.x * 256 + threadIdx.x;
    float4 v = ((const float4*)x)[i];
    ((float4*)out)[i] = v;
    __half2 p0 = __floats2half2_rn(v.x, v.y);
    __half2 p1 = __floats2half2_rn(v.z, v.w);
    ((__half2*)g_Xb)[2 * i]     = p0;
    ((__half2*)g_Xb)[2 * i + 1] = p1;
}

__global__ void pack_w(const float* __restrict__ kf, const float* __restrict__ kg,
                       const float* __restrict__ kh) {
    int idx = blockIdx.x * 256 + threadIdx.x;
    int n = idx >> 9, k = idx & 511;
    float v;
    if (n < 64)       v = kf[k * 64 + n];
    else if (n < 128) v = kg[k * 64 + (n - 64)];
    else              v = kh[k * 512 + (n - 128)];
    g_Wt[idx] = __float2half(v);
    if (idx < NROWS) g_l[idx] = 0.f;       // folded zero_l
}

// ---------------------------------------------------------------------------
// GEMM 1: [f|g|v] = Xb @ W ; f/g -> g_FG, v -> g_V (natural, coalesced)
// ---------------------------------------------------------------------------
__global__ void __launch_bounds__(256, 3) gemm1_qkv() {
    extern __shared__ __half smem[];
    uint32_t acc[2][8][2];
    #pragma unroll
    for (int i = 0; i < 2; i++)
        #pragma unroll
        for (int j = 0; j < 8; j++) { acc[i][j][0] = 0u; acc[i][j][1] = 0u; }

    const int m0 = blockIdx.y * 128, n0 = blockIdx.x * 128;
    gemm_tile(g_Xb + (size_t)m0 * Cc, Cc, g_Wt + (size_t)n0 * Cc, Cc, Cc, acc, smem);

    const int lane = threadIdx.x & 31, warp = threadIdx.x >> 5;
    const int wm = warp & 3, wn = warp >> 2, g = lane >> 2, t4 = lane & 3;
    #pragma unroll
    for (int i = 0; i < 2; i++) {
        #pragma unroll
        for (int h = 0; h < 2; h++) {
            int r = m0 + wm * 32 + i * 16 + g + h * 8;
            #pragma unroll
            for (int j = 0; j < 8; j++) {
                int c = n0 + wn * 64 + j * 8 + 2 * t4;
                uint32_t p = acc[i][j][h];          // half2 at (r, c..c+1)
                if (n0 == 0) *(uint32_t*)&g_FG[(size_t)r * 128 + c] = p;
                else         *(uint32_t*)&g_V [(size_t)r * Cc + (c - 128)] = p;
            }
        }
    }
}

// ---------------------------------------------------------------------------
// Transpose V [b][i][c] -> Vt [b][c][i] (smem tiled, coalesced both sides)
// ---------------------------------------------------------------------------
__global__ void vtrans() {
    __shared__ __half t[64 * 72];
    const int bb = blockIdx.z, it = blockIdx.x, ct = blockIdx.y;
    const __half* src = g_V + ((size_t)bb * Np + it * 64) * Cc + ct * 64;
    #pragma unroll
    for (int k = 0; k < 2; k++) {
        int u = threadIdx.x + k * 256;
        int row = u >> 3, c8 = (u & 7) * 8;
        *(uint4*)(t + row * 72 + c8) = *(const uint4*)(src + (size_t)row * Cc + c8);
    }
    __syncthreads();
    __half* dst = g_Vt + ((size_t)bb * Cc + ct * 64) * Np + it * 64;
    #pragma unroll
    for (int k = 0; k < 2; k++) {
        int u = threadIdx.x + k * 256;
        int orow = u >> 3, i8 = (u & 7) * 8;
        __half tmp[8];
        #pragma unroll
        for (int q = 0; q < 8; q++) tmp[q] = t[(i8 + q) * 72 + orow];
        *(uint4*)(dst + (size_t)orow * Np + i8) = *(uint4*)tmp;
    }
}

// ---------------------------------------------------------------------------
// GEMM 2: P = 2^(S*log2e - 4) per batch (fp16 ex2 fast path), + fused row-sums
// ---------------------------------------------------------------------------
__global__ void __launch_bounds__(256, 3) gemm2_score() {
    extern __shared__ __half smem[];
    uint32_t acc[2][8][2];
    #pragma unroll
    for (int i = 0; i < 2; i++)
        #pragma unroll
        for (int j = 0; j < 8; j++) { acc[i][j][0] = 0u; acc[i][j][1] = 0u; }

    const int n0 = blockIdx.x * 128, m0 = blockIdx.y * 128, bb = blockIdx.z;
    const __half* A  = g_FG + ((size_t)bb * Np + m0) * 128;       // f
    const __half* Bp = g_FG + ((size_t)bb * Np + n0) * 128 + 64;  // g
    gemm_tile(A, 128, Bp, 128, 64, acc, smem);

    __half* Pb = g_P + (size_t)bb * Np * Np;
    const int lane = threadIdx.x & 31, warp = threadIdx.x >> 5;
    const int wm = warp & 3, wn = warp >> 2, g = lane >> 2, t4 = lane & 3;

    // p = 2^(s*log2e - 4)  (== exp(s)/16), all in fp16x2
    __half2 cl = __floats2half2_rn(1.44269504f, 1.44269504f);
    __half2 cm = __floats2half2_rn(-4.f, -4.f);
    const uint32_t clu = *(uint32_t*)&cl;
    const uint32_t cmu = *(uint32_t*)&cm;

    #pragma unroll
    for (int i = 0; i < 2; i++) {
        #pragma unroll
        for (int h = 0; h < 2; h++) {
            int r = m0 + wm * 32 + i * 16 + g + h * 8;
            float rs = 0.f;
            #pragma unroll
            for (int j = 0; j < 8; j++) {
                int c = n0 + wn * 64 + j * 8 + 2 * t4;
                uint32_t eu, pu;
                asm("fma.rn.f16x2 %0, %1, %2, %3;"
                    : "=r"(eu) : "r"(acc[i][j][h]), "r"(clu), "r"(cmu));
                asm("ex2.approx.f16x2 %0, %1;" : "=r"(pu) : "r"(eu));
                *(uint32_t*)&Pb[(size_t)r * Np + c] = pu;
                float2 pf = __half22float2(*(__half2*)&pu);  // stored bits -> exact l
                rs += pf.x + pf.y;
            }
            rs += __shfl_down_sync(0xffffffffu, rs, 2, 4);
            rs += __shfl_down_sync(0xffffffffu, rs, 1, 4);
            if (t4 == 0) atomicAdd(&g_l[(size_t)bb * Np + r], rs);
        }
    }
}

// ---------------------------------------------------------------------------
// GEMM 3 (split-K=4): out += gamma * (P @ Vt^T)_partial / l
// out pre-initialized to x in convert_x. blockIdx.z = b*KSPLIT + s.
// float2 vector atomics (sm_90+) halve the RED instruction count.
// ---------------------------------------------------------------------------
__global__ void __launch_bounds__(256, 3) gemm3_out(
    const float* __restrict__ gamma, float* __restrict__ out)
{
    extern __shared__ __half smem[];
    uint32_t acc[2][8][2];
    #pragma unroll
    for (int i = 0; i < 2; i++)
        #pragma unroll
        for (int j = 0; j < 8; j++) { acc[i][j][0] = 0u; acc[i][j][1] = 0u; }

    const int n0 = blockIdx.x * 128, m0 = blockIdx.y * 128;
    const int bb = blockIdx.z / KSPLIT, sp = blockIdx.z % KSPLIT;
    const int kof = sp * (Np / KSPLIT);          // 1024-wide K slice
    const __half* A  = g_P  + ((size_t)bb * Np + m0) * Np + kof;
    const __half* Bp = g_Vt + ((size_t)bb * Cc + n0) * Np + kof;
    gemm_tile(A, Np, Bp, Np, Np / KSPLIT, acc, smem);

    const float gam = gamma[0];
    const int lane = threadIdx.x & 31, warp = threadIdx.x >> 5;
    const int wm = warp & 3, wn = warp >> 2, g = lane >> 2, t4 = lane & 3;

    #pragma unroll
    for (int i = 0; i < 2; i++) {
        #pragma unroll
        for (int h = 0; h < 2; h++) {
            int r = bb * Np + m0 + wm * 32 + i * 16 + g + h * 8;
            float inv = gam / g_l[r];
            #pragma unroll
            for (int j = 0; j < 8; j++) {
                int c = n0 + wn * 64 + j * 8 + 2 * t4;
                size_t o = (size_t)r * Cc + c;
                float2 a2 = __half22float2(*(__half2*)&acc[i][j][h]);
                atomicAdd((float2*)&out[o], make_float2(a2.x * inv, a2.y * inv));
            }
        }
    }
}

// ===========================================================================
extern "C" void kernel_launch(void* const* d_in, const int* in_sizes, int n_in,
                              void* d_out, int out_size) {
    const float* x     = (const float*)d_in[0];
    const float* kf    = (const float*)d_in[1];
    const float* kg    = (const float*)d_in[2];
    const float* kh    = (const float*)d_in[3];
    const float* gamma = (const float*)d_in[4];
    float* out = (float*)d_out;

    static bool attr_done = false;
    if (!attr_done) {
        cudaFuncSetAttribute(gemm1_qkv,   cudaFuncAttributeMaxDynamicSharedMemorySize, GEMM_SMEM);
        cudaFuncSetAttribute(gemm2_score, cudaFuncAttributeMaxDynamicSharedMemorySize, GEMM_SMEM);
        cudaFuncSetAttribute(gemm3_out,   cudaFuncAttributeMaxDynamicSharedMemorySize, GEMM_SMEM);
        attr_done = true;
    }

    convert_x<<<(NROWS * Cc / 4) / 256, 256>>>(x, out);   // also: out = x
    pack_w<<<(NW * Cc) / 256, 256>>>(kf, kg, kh);         // also: g_l = 0
    gemm1_qkv<<<dim3(NW / 128, NROWS / 128), 256, GEMM_SMEM>>>();
    vtrans<<<dim3(64, 8, 4), 256>>>();
    gemm2_score<<<dim3(Np / 128, Np / 128, Bn), 256, GEMM_SMEM>>>();
    gemm3_out<<<dim3(Cc / 128, Np / 128, Bn * KSPLIT), 256, GEMM_SMEM>>>(gamma, out);
}

// round 12
// speedup vs baseline: 1.1449x; 1.0652x over previous
#include <cuda_runtime.h>
#include <cuda_bf16.h>
#include <cuda_fp16.h>
#include <cstdint>

// Problem constants
#define Bn 4
#define Np 4096      // pixels per batch (64*64)
#define Cc 512
#define NW 640       // packed QKV output width: 64 f + 64 g + 512 v
#define NROWS (Bn*Np)
#define KSPLIT 4         // gemm3 split-K factor (wave-quantization fix)
// P stored as exp(s)/16 = 2^(s*log2e - 4); the /16 cancels in P@V / rowsum(P)

// Scratch (static device allocations -- allowed)
__device__ __align__(1024) __half g_Xb[(size_t)NROWS * Cc];   // x in fp16
__device__ __align__(1024) __half g_Wt[(size_t)NW * Cc];      // packed weights [n][k]
__device__ __align__(1024) __half g_FG[(size_t)NROWS * 128];  // f (0-63), g (64-127)
__device__ __align__(1024) __half g_V [(size_t)Bn * Np * Cc]; // V natural [b][i][c]
__device__ __align__(1024) __half g_P [(size_t)Bn * Np * Np]; // exp(S)/16, fp16
__device__ float g_l[NROWS];                                  // row sums of stored P

// ---------------------------------------------------------------------------
// mma.sync m16n8k16 fp16 -> fp16 accum
// ---------------------------------------------------------------------------
__device__ __forceinline__ void mma_f16(uint32_t c[2], const uint32_t a[4],
                                        uint32_t b0, uint32_t b1) {
    asm volatile(
        "mma.sync.aligned.m16n8k16.row.col.f16.f16.f16.f16 "
        "{%0,%1}, {%2,%3,%4,%5}, {%6,%7}, {%0,%1};\n"
        : "+r"(c[0]), "+r"(c[1])
        : "r"(a[0]), "r"(a[1]), "r"(a[2]), "r"(a[3]), "r"(b0), "r"(b1));
}
__device__ __forceinline__ void ldsm4(uint32_t* r, uint32_t addr) {
    asm volatile("ldmatrix.sync.aligned.m8n8.x4.shared.b16 {%0,%1,%2,%3}, [%4];"
                 : "=r"(r[0]), "=r"(r[1]), "=r"(r[2]), "=r"(r[3]) : "r"(addr));
}
__device__ __forceinline__ void ldsm4t(uint32_t* r, uint32_t addr) {
    asm volatile("ldmatrix.sync.aligned.m8n8.x4.trans.shared.b16 {%0,%1,%2,%3}, [%4];"
                 : "=r"(r[0]), "=r"(r[1]), "=r"(r[2]), "=r"(r[3]) : "r"(addr));
}
__device__ __forceinline__ uint32_t smem_to_u32(const void* p) {
    uint32_t a;
    asm("{ .reg .u64 t; cvta.to.shared.u64 t, %1; cvt.u32.u64 %0, t; }" : "=r"(a) : "l"(p));
    return a;
}
__device__ __forceinline__ void cp16(uint32_t dst, const void* src) {
    asm volatile("cp.async.cg.shared.global [%0], [%1], 16;\n" :: "r"(dst), "l"(src));
}
#define CP_COMMIT() asm volatile("cp.async.commit_group;\n" ::: "memory")
#define CP_WAIT0()  asm volatile("cp.async.wait_group 0;\n" ::: "memory")

#define TKE   64                 // K-tile in fp16 elements (128 bytes per row)
#define TILEB (128 * 128)        // bytes per staged tile (16 KB)
#define GEMM_SMEM (2 * 2 * TILEB)   // 65536 bytes -> 3 CTAs/SM

// Block tile 128x128, K-tile 64, 256 threads (8 warps, 4x2 grid, 32x64 each).
// SW128 XOR-swizzled stages, cp.async double buffer, ONE barrier per K-tile.
// (R8 core: proven config -- used by gemm1/gemm2, unchanged)
__device__ __forceinline__ void gemm_tile(
    const __half* __restrict__ Ag, int lda,
    const __half* __restrict__ Bg, int ldb,
    int K, uint32_t acc[2][8][2], __half* smem)
{
    const int tid = threadIdx.x, lane = tid & 31, warp = tid >> 5;
    const int wm = warp & 3, wn = warp >> 2;
    const uint32_t sbase = smem_to_u32(smem);
    const int srow = tid >> 3;          // staging row 0..31 (+32*q)
    const int schunk = tid & 7;         // 16B chunk within 128B row
    const int nk = K / TKE;

    const uint32_t l7  = lane & 7;
    const uint32_t hiA = lane >> 4;            // A: k-half from lane
    const uint32_t hiB = (lane >> 3) & 1;      // B: k-half from lane
    const uint32_t rowA = (uint32_t)(wm * 32 + ((lane >> 3) & 1) * 8) + l7;
    const uint32_t rowB = (uint32_t)(wn * 64 + (lane >> 4) * 8) + l7;

    auto issue = [&](int i) {
        const uint32_t sa = sbase + (uint32_t)((i & 1) * 2 * TILEB);
        const uint32_t sb = sa + TILEB;
        const int k0 = i * TKE;
        const uint32_t pch = (uint32_t)(schunk ^ (srow & 7)) * 16;
        #pragma unroll
        for (int q = 0; q < 4; q++) {
            const int row = srow + q * 32;
            const uint32_t soff = (uint32_t)row * 128 + pch;
            cp16(sa + soff, (const char*)(Ag + (size_t)row * lda + k0) + schunk * 16);
            cp16(sb + soff, (const char*)(Bg + (size_t)row * ldb + k0) + schunk * 16);
        }
        CP_COMMIT();
    };

    issue(0);   // prologue

    for (int i = 0; i < nk; i++) {
        CP_WAIT0();
        __syncthreads();                 // single barrier per K-tile
        if (i + 1 < nk) issue(i + 1);

        const uint32_t bb = sbase + (uint32_t)((i & 1) * 2 * TILEB);
        #pragma unroll
        for (int ks = 0; ks < 4; ks++) {             // four k16 steps
            const uint32_t pa = (((uint32_t)(2 * ks) + hiA) ^ l7) << 4;
            const uint32_t pb = (((uint32_t)(2 * ks) + hiB) ^ l7) << 4;
            uint32_t a[2][4], b4[4][4];
            ldsm4(a[0], bb + rowA * 128 + pa);
            ldsm4(a[1], bb + (rowA + 16) * 128 + pa);
            #pragma unroll
            for (int jp = 0; jp < 4; jp++)
                ldsm4(b4[jp], bb + TILEB + (rowB + (uint32_t)(jp * 16)) * 128 + pb);
            #pragma unroll
            for (int ii = 0; ii < 2; ii++)
                #pragma unroll
                for (int jp = 0; jp < 4; jp++) {
                    mma_f16(acc[ii][2 * jp],     a[ii], b4[jp][0], b4[jp][1]);
                    mma_f16(acc[ii][2 * jp + 1], a[ii], b4[jp][2], b4[jp][3]);
                }
        }
    }
    __syncthreads();
}

// ---------------------------------------------------------------------------
// Prep kernels
// ---------------------------------------------------------------------------
// convert x -> fp16 AND pre-initialize out = x (gemm3 splits atomicAdd into it)
__global__ void convert_x(const float* __restrict__ x, float* __restrict__ out) {
    size_t i = (size_t)blockIdx.x * 256 + threadIdx.x;
    float4 v = ((const float4*)x)[i];
    ((float4*)out)[i] = v;
    __half2 p0 = __floats2half2_rn(v.x, v.y);
    __half2 p1 = __floats2half2_rn(v.z, v.w);
    ((__half2*)g_Xb)[2 * i]     = p0;
    ((__half2*)g_Xb)[2 * i + 1] = p1;
}

__global__ void pack_w(const float* __restrict__ kf, const float* __restrict__ kg,
                       const float* __restrict__ kh) {
    int idx = blockIdx.x * 256 + threadIdx.x;
    int n = idx >> 9, k = idx & 511;
    float v;
    if (n < 64)       v = kf[k * 64 + n];
    else if (n < 128) v = kg[k * 64 + (n - 64)];
    else              v = kh[k * 512 + (n - 128)];
    g_Wt[idx] = __float2half(v);
    if (idx < NROWS) g_l[idx] = 0.f;       // folded zero_l
}

// ---------------------------------------------------------------------------
// GEMM 1: [f|g|v] = Xb @ W ; f/g -> g_FG, v -> g_V (natural, coalesced)
// ---------------------------------------------------------------------------
__global__ void __launch_bounds__(256, 3) gemm1_qkv() {
    extern __shared__ __half smem[];
    uint32_t acc[2][8][2];
    #pragma unroll
    for (int i = 0; i < 2; i++)
        #pragma unroll
        for (int j = 0; j < 8; j++) { acc[i][j][0] = 0u; acc[i][j][1] = 0u; }

    const int m0 = blockIdx.y * 128, n0 = blockIdx.x * 128;
    gemm_tile(g_Xb + (size_t)m0 * Cc, Cc, g_Wt + (size_t)n0 * Cc, Cc, Cc, acc, smem);

    const int lane = threadIdx.x & 31, warp = threadIdx.x >> 5;
    const int wm = warp & 3, wn = warp >> 2, g = lane >> 2, t4 = lane & 3;
    #pragma unroll
    for (int i = 0; i < 2; i++) {
        #pragma unroll
        for (int h = 0; h < 2; h++) {
            int r = m0 + wm * 32 + i * 16 + g + h * 8;
            #pragma unroll
            for (int j = 0; j < 8; j++) {
                int c = n0 + wn * 64 + j * 8 + 2 * t4;
                uint32_t p = acc[i][j][h];          // half2 at (r, c..c+1)
                if (n0 == 0) *(uint32_t*)&g_FG[(size_t)r * 128 + c] = p;
                else         *(uint32_t*)&g_V [(size_t)r * Cc + (c - 128)] = p;
            }
        }
    }
}

// ---------------------------------------------------------------------------
// GEMM 2: P = 2^(S*log2e - 4) per batch (fp16 ex2 fast path), + fused row-sums
// ---------------------------------------------------------------------------
__global__ void __launch_bounds__(256, 3) gemm2_score() {
    extern __shared__ __half smem[];
    uint32_t acc[2][8][2];
    #pragma unroll
    for (int i = 0; i < 2; i++)
        #pragma unroll
        for (int j = 0; j < 8; j++) { acc[i][j][0] = 0u; acc[i][j][1] = 0u; }

    const int n0 = blockIdx.x * 128, m0 = blockIdx.y * 128, bb = blockIdx.z;
    const __half* A  = g_FG + ((size_t)bb * Np + m0) * 128;       // f
    const __half* Bp = g_FG + ((size_t)bb * Np + n0) * 128 + 64;  // g
    gemm_tile(A, 128, Bp, 128, 64, acc, smem);

    __half* Pb = g_P + (size_t)bb * Np * Np;
    const int lane = threadIdx.x & 31, warp = threadIdx.x >> 5;
    const int wm = warp & 3, wn = warp >> 2, g = lane >> 2, t4 = lane & 3;

    // p = 2^(s*log2e - 4)  (== exp(s)/16), all in fp16x2
    __half2 cl = __floats2half2_rn(1.44269504f, 1.44269504f);
    __half2 cm = __floats2half2_rn(-4.f, -4.f);
    const uint32_t clu = *(uint32_t*)&cl;
    const uint32_t cmu = *(uint32_t*)&cm;

    #pragma unroll
    for (int i = 0; i < 2; i++) {
        #pragma unroll
        for (int h = 0; h < 2; h++) {
            int r = m0 + wm * 32 + i * 16 + g + h * 8;
            float rs = 0.f;
            #pragma unroll
            for (int j = 0; j < 8; j++) {
                int c = n0 + wn * 64 + j * 8 + 2 * t4;
                uint32_t eu, pu;
                asm("fma.rn.f16x2 %0, %1, %2, %3;"
                    : "=r"(eu) : "r"(acc[i][j][h]), "r"(clu), "r"(cmu));
                asm("ex2.approx.f16x2 %0, %1;" : "=r"(pu) : "r"(eu));
                *(uint32_t*)&Pb[(size_t)r * Np + c] = pu;
                float2 pf = __half22float2(*(__half2*)&pu);  // stored bits -> exact l
                rs += pf.x + pf.y;
            }
            rs += __shfl_down_sync(0xffffffffu, rs, 2, 4);
            rs += __shfl_down_sync(0xffffffffu, rs, 1, 4);
            if (t4 == 0) atomicAdd(&g_l[(size_t)bb * Np + r], rs);
        }
    }
}

// ---------------------------------------------------------------------------
// GEMM 3 (split-K=4): out += gamma * (P @ V)_partial / l
// B = V in NATURAL [pixel][channel] layout -- fragments via ldmatrix.trans
// (vtrans kernel eliminated). out pre-initialized to x in convert_x.
// B stage: 64 k-rows x 256B (16 KB), row-XOR swizzle; A stage as usual.
// ---------------------------------------------------------------------------
__global__ void __launch_bounds__(256, 3) gemm3_out(
    const float* __restrict__ gamma, float* __restrict__ out)
{
    extern __shared__ __half smem[];
    uint32_t acc[2][8][2];
    #pragma unroll
    for (int i = 0; i < 2; i++)
        #pragma unroll
        for (int j = 0; j < 8; j++) { acc[i][j][0] = 0u; acc[i][j][1] = 0u; }

    const int tid = threadIdx.x, lane = tid & 31, warp = tid >> 5;
    const int wm = warp & 3, wn = warp >> 2;
    const int n0 = blockIdx.x * 128, m0 = blockIdx.y * 128;
    const int bb = blockIdx.z / KSPLIT, sp = blockIdx.z % KSPLIT;
    const int kof = sp * (Np / KSPLIT);          // 1024-wide K slice
    const __half* Ag = g_P + ((size_t)bb * Np + m0) * Np + kof;       // [m][k]
    const __half* Bv = g_V + ((size_t)(bb * Np + kof)) * Cc + n0;     // [k][c]

    const uint32_t sbase = smem_to_u32(smem);
    const int nk = (Np / KSPLIT) / TKE;          // 16

    // A staging lanes (128 rows x 128B): 8 threads/row
    const int srA = tid >> 3, scA = tid & 7;
    const uint32_t pchA = (uint32_t)(scA ^ (srA & 7)) * 16;
    // B staging lanes (64 rows x 256B): 16 threads/row
    const int srB = tid >> 4, scB = tid & 15;
    const uint32_t pchB = (uint32_t)(((scB & 7) ^ (srB & 7)) | (scB & 8)) * 16;

    // A fragment lanes (as in gemm_tile)
    const uint32_t l7  = lane & 7;
    const uint32_t hiA = lane >> 4;
    const uint32_t rowA = (uint32_t)(wm * 32 + ((lane >> 3) & 1) * 8) + l7;
    // B fragment lanes (trans path): kl = k-row within k16 (0..15), clB = n+8 half
    const uint32_t kl  = lane & 15;
    const uint32_t clB = lane >> 4;
    const uint32_t kl7 = kl & 7;
    const uint32_t bfb = kl * 256 + (uint32_t)wn * 128;   // per-lane B base bytes

    auto issue = [&](int i) {
        const uint32_t sa = sbase + (uint32_t)((i & 1) * 2 * TILEB);
        const uint32_t sb = sa + TILEB;
        const int k0 = i * TKE;
        #pragma unroll
        for (int q = 0; q < 4; q++) {             // A: 128 rows
            const int row = srA + q * 32;
            cp16(sa + (uint32_t)row * 128 + pchA,
                 (const char*)(Ag + (size_t)row * Np + k0) + scA * 16);
        }
        #pragma unroll
        for (int q = 0; q < 4; q++) {             // B: 64 k-rows x 256B
            const int row = srB + q * 16;
            cp16(sb + (uint32_t)row * 256 + pchB,
                 (const char*)(Bv + (size_t)(k0 + row) * Cc) + scB * 16);
        }
        CP_COMMIT();
    };

    issue(0);   // prologue

    for (int i = 0; i < nk; i++) {
        CP_WAIT0();
        __syncthreads();                 // single barrier per K-tile
        if (i + 1 < nk) issue(i + 1);

        const uint32_t bbuf = sbase + (uint32_t)((i & 1) * 2 * TILEB);
        #pragma unroll
        for (int ks = 0; ks < 4; ks++) {             // four k16 steps
            const uint32_t pa = (((uint32_t)(2 * ks) + hiA) ^ l7) << 4;
            uint32_t a[2][4], b4[4][4];
            ldsm4(a[0], bbuf + rowA * 128 + pa);
            ldsm4(a[1], bbuf + (rowA + 16) * 128 + pa);
            const uint32_t bks = bbuf + TILEB + bfb + (uint32_t)ks * 4096;
            #pragma unroll
            for (int jp = 0; jp < 4; jp++) {
                const uint32_t sw = (((uint32_t)(jp * 2) | clB) ^ kl7) << 4;
                ldsm4t(b4[jp], bks + sw);
            }
            #pragma unroll
            for (int ii = 0; ii < 2; ii++)
                #pragma unroll
                for (int jp = 0; jp < 4; jp++) {
                    mma_f16(acc[ii][2 * jp],     a[ii], b4[jp][0], b4[jp][1]);
                    mma_f16(acc[ii][2 * jp + 1], a[ii], b4[jp][2], b4[jp][3]);
                }
        }
    }

    const float gam = gamma[0];
    const int g = lane >> 2, t4 = lane & 3;
    #pragma unroll
    for (int i = 0; i < 2; i++) {
        #pragma unroll
        for (int h = 0; h < 2; h++) {
            int r = bb * Np + m0 + wm * 32 + i * 16 + g + h * 8;
            float inv = gam / g_l[r];
            #pragma unroll
            for (int j = 0; j < 8; j++) {
                int c = n0 + wn * 64 + j * 8 + 2 * t4;
                size_t o = (size_t)r * Cc + c;
                float2 a2 = __half22float2(*(__half2*)&acc[i][j][h]);
                atomicAdd((float2*)&out[o], make_float2(a2.x * inv, a2.y * inv));
            }
        }
    }
}

// ===========================================================================
extern "C" void kernel_launch(void* const* d_in, const int* in_sizes, int n_in,
                              void* d_out, int out_size) {
    const float* x     = (const float*)d_in[0];
    const float* kf    = (const float*)d_in[1];
    const float* kg    = (const float*)d_in[2];
    const float* kh    = (const float*)d_in[3];
    const float* gamma = (const float*)d_in[4];
    float* out = (float*)d_out;

    static bool attr_done = false;
    if (!attr_done) {
        cudaFuncSetAttribute(gemm1_qkv,   cudaFuncAttributeMaxDynamicSharedMemorySize, GEMM_SMEM);
        cudaFuncSetAttribute(gemm2_score, cudaFuncAttributeMaxDynamicSharedMemorySize, GEMM_SMEM);
        cudaFuncSetAttribute(gemm3_out,   cudaFuncAttributeMaxDynamicSharedMemorySize, GEMM_SMEM);
        attr_done = true;
    }

    convert_x<<<(NROWS * Cc / 4) / 256, 256>>>(x, out);   // also: out = x
    pack_w<<<(NW * Cc) / 256, 256>>>(kf, kg, kh);         // also: g_l = 0
    gemm1_qkv<<<dim3(NW / 128, NROWS / 128), 256, GEMM_SMEM>>>();
    gemm2_score<<<dim3(Np / 128, Np / 128, Bn), 256, GEMM_SMEM>>>();
    gemm3_out<<<dim3(Cc / 128, Np / 128, Bn * KSPLIT), 256, GEMM_SMEM>>>(gamma, out);
}